// round 4
// baseline (speedup 1.0000x reference)
#include <cuda_runtime.h>
#include <math.h>

// Problem constants
#define BATCH 4
#define T_SEQ 2048
#define EDIM  1024
#define HEADS 16
#define HDIM  64
#define MTOT  (BATCH * T_SEQ)   // 8192 rows

// ---------------------------------------------------------------------------
// Scratch (allocation-free rule: __device__ globals)
// ---------------------------------------------------------------------------
__device__ float g_Q[(size_t)MTOT * EDIM];
__device__ float g_K[(size_t)MTOT * EDIM];
__device__ float g_V[(size_t)MTOT * EDIM];
__device__ float g_A[(size_t)MTOT * EDIM];

// ---------------------------------------------------------------------------
// Helpers: tf32 convert + mma.sync m16n8k8 tf32
// ---------------------------------------------------------------------------
__device__ __forceinline__ unsigned f2tf(float x) {
    unsigned u;
    asm("cvt.rna.tf32.f32 %0, %1;" : "=r"(u) : "f"(x));
    return u;
}
__device__ __forceinline__ float f2tff(float x) { return __uint_as_float(f2tf(x)); }

__device__ __forceinline__ void mma8(float* c, const unsigned* a, const unsigned* b) {
    asm volatile(
        "mma.sync.aligned.m16n8k8.row.col.f32.tf32.tf32.f32 "
        "{%0,%1,%2,%3}, {%4,%5,%6,%7}, {%8,%9}, {%0,%1,%2,%3};\n"
        : "+f"(c[0]), "+f"(c[1]), "+f"(c[2]), "+f"(c[3])
        : "r"(a[0]), "r"(a[1]), "r"(a[2]), "r"(a[3]), "r"(b[0]), "r"(b[1]));
}

// ---------------------------------------------------------------------------
// GEMM: Y[M,N] = X[M,K] @ W[N,K]^T + bias    (M = 8192 via grid, K=N=1024)
// Block tile 128x128x32, 8 warps (2x4), warp tile 64x32.
// ---------------------------------------------------------------------------
#define BM 128
#define BN 128
#define BKC 32
#define ASTR (BKC + 4)   // 36 floats: A/B fragment LDS conflict-free

__global__ __launch_bounds__(256, 2)
void gemm_bias(const float* __restrict__ X, const float* __restrict__ W,
               const float* __restrict__ bias, float* __restrict__ Y,
               int K, int N)
{
    __shared__ float As[BM * ASTR];
    __shared__ float Bs[BN * ASTR];

    const int bm = blockIdx.y * BM;
    const int bn = blockIdx.x * BN;
    const int tid  = threadIdx.x;
    const int lane = tid & 31;
    const int warp = tid >> 5;
    const int wm = (warp >> 2) * 64;   // warp row offset in tile
    const int wn = (warp & 3) * 32;    // warp col offset in tile

    float acc[4][4][4];
#pragma unroll
    for (int mt = 0; mt < 4; mt++)
#pragma unroll
        for (int nt = 0; nt < 4; nt++)
#pragma unroll
            for (int r = 0; r < 4; r++) acc[mt][nt][r] = 0.f;

    for (int kb = 0; kb < K; kb += BKC) {
        // Stage tiles (convert to tf32 on the way in)
#pragma unroll
        for (int i = 0; i < 4; i++) {
            int idx = i * 256 + tid;
            int r = idx >> 3;
            int c = (idx & 7) * 4;
            float4 v = *reinterpret_cast<const float4*>(X + (size_t)(bm + r) * K + kb + c);
            As[r * ASTR + c + 0] = f2tff(v.x);
            As[r * ASTR + c + 1] = f2tff(v.y);
            As[r * ASTR + c + 2] = f2tff(v.z);
            As[r * ASTR + c + 3] = f2tff(v.w);
            float4 w = *reinterpret_cast<const float4*>(W + (size_t)(bn + r) * K + kb + c);
            Bs[r * ASTR + c + 0] = f2tff(w.x);
            Bs[r * ASTR + c + 1] = f2tff(w.y);
            Bs[r * ASTR + c + 2] = f2tff(w.z);
            Bs[r * ASTR + c + 3] = f2tff(w.w);
        }
        __syncthreads();

#pragma unroll
        for (int ks = 0; ks < 4; ks++) {
            unsigned afr[4][4], bfr[4][2];
#pragma unroll
            for (int mt = 0; mt < 4; mt++) {
                const float* p = &As[(wm + mt * 16 + (lane >> 2)) * ASTR + ks * 8 + (lane & 3)];
                afr[mt][0] = __float_as_uint(p[0]);
                afr[mt][1] = __float_as_uint(p[8 * ASTR]);
                afr[mt][2] = __float_as_uint(p[4]);
                afr[mt][3] = __float_as_uint(p[8 * ASTR + 4]);
            }
#pragma unroll
            for (int nt = 0; nt < 4; nt++) {
                const float* p = &Bs[(wn + nt * 8 + (lane >> 2)) * ASTR + ks * 8 + (lane & 3)];
                bfr[nt][0] = __float_as_uint(p[0]);
                bfr[nt][1] = __float_as_uint(p[4]);
            }
#pragma unroll
            for (int mt = 0; mt < 4; mt++)
#pragma unroll
                for (int nt = 0; nt < 4; nt++)
                    mma8(acc[mt][nt], afr[mt], bfr[nt]);
        }
        __syncthreads();
    }

    // Epilogue: += bias, write fp32
#pragma unroll
    for (int mt = 0; mt < 4; mt++) {
        int row = bm + wm + mt * 16 + (lane >> 2);
#pragma unroll
        for (int nt = 0; nt < 4; nt++) {
            int col = bn + wn + nt * 8 + 2 * (lane & 3);
            float b0 = bias[col], b1 = bias[col + 1];
            Y[(size_t)row * N + col]           = acc[mt][nt][0] + b0;
            Y[(size_t)row * N + col + 1]       = acc[mt][nt][1] + b1;
            Y[(size_t)(row + 8) * N + col]     = acc[mt][nt][2] + b0;
            Y[(size_t)(row + 8) * N + col + 1] = acc[mt][nt][3] + b1;
        }
    }
}

// ---------------------------------------------------------------------------
// Flash attention: per (b,h), 128-row Q tile, stream 64-key chunks.
// Q/K/V layout: [B*T, E] with head h at column offset h*64 (no transpose).
// 4 warps, each owns 32 q-rows. S and O accumulate in C-fragments; P goes
// through smem (tf32) to re-fragment as A for the PV mma.
// ---------------------------------------------------------------------------
#define QT 128
#define KC 64
#define DSTR (HDIM + 4)   // 68

__global__ __launch_bounds__(128, 2)
void attn_kernel(const float* __restrict__ Qg, const float* __restrict__ Kg,
                 const float* __restrict__ Vg, float* __restrict__ Oa)
{
    extern __shared__ float sm[];
    float* sQ = sm;                    // QT*DSTR
    float* sK = sQ + QT * DSTR;        // KC*DSTR
    float* sV = sK + KC * DSTR;        // KC*DSTR
    float* sP = sV + KC * DSTR;        // QT*DSTR

    const int tid  = threadIdx.x;
    const int lane = tid & 31;
    const int warp = tid >> 5;
    const int bh = blockIdx.y;
    const int b  = bh >> 4;
    const int h  = bh & 15;
    const int q0 = blockIdx.x * QT;
    const size_t base = (size_t)b * T_SEQ * EDIM + (size_t)h * HDIM;
    const int wq = warp * 32;

    // Load Q tile, pre-scaled by 1/sqrt(D)=0.125, tf32
    for (int i = tid; i < QT * HDIM / 4; i += 128) {
        int r = i >> 4;
        int c = (i & 15) * 4;
        float4 v = *reinterpret_cast<const float4*>(Qg + base + (size_t)(q0 + r) * EDIM + c);
        float* d = &sQ[r * DSTR + c];
        d[0] = f2tff(v.x * 0.125f);
        d[1] = f2tff(v.y * 0.125f);
        d[2] = f2tff(v.z * 0.125f);
        d[3] = f2tff(v.w * 0.125f);
    }

    float oacc[2][8][4];
#pragma unroll
    for (int mt = 0; mt < 2; mt++)
#pragma unroll
        for (int nt = 0; nt < 8; nt++)
#pragma unroll
            for (int r = 0; r < 4; r++) oacc[mt][nt][r] = 0.f;
    float mrow[2][2] = {{-1e30f, -1e30f}, {-1e30f, -1e30f}};
    float lrow[2][2] = {{0.f, 0.f}, {0.f, 0.f}};

    for (int kc = 0; kc < T_SEQ; kc += KC) {
        // Stage K and V chunks (tf32)
        for (int i = tid; i < KC * HDIM / 4; i += 128) {
            int r = i >> 4;
            int c = (i & 15) * 4;
            float4 kv = *reinterpret_cast<const float4*>(Kg + base + (size_t)(kc + r) * EDIM + c);
            float* dk = &sK[r * DSTR + c];
            dk[0] = f2tff(kv.x); dk[1] = f2tff(kv.y); dk[2] = f2tff(kv.z); dk[3] = f2tff(kv.w);
            float4 vv = *reinterpret_cast<const float4*>(Vg + base + (size_t)(kc + r) * EDIM + c);
            float* dv = &sV[r * DSTR + c];
            dv[0] = f2tff(vv.x); dv[1] = f2tff(vv.y); dv[2] = f2tff(vv.z); dv[3] = f2tff(vv.w);
        }
        __syncthreads();

        // S = Q @ K^T  (M=128 per block, warp 32 rows; N=64 keys; K=64 dims)
        float sacc[2][8][4];
#pragma unroll
        for (int mt = 0; mt < 2; mt++)
#pragma unroll
            for (int nt = 0; nt < 8; nt++)
#pragma unroll
                for (int r = 0; r < 4; r++) sacc[mt][nt][r] = 0.f;

#pragma unroll
        for (int ks = 0; ks < 8; ks++) {
            unsigned afr[2][4], bfr[8][2];
#pragma unroll
            for (int mt = 0; mt < 2; mt++) {
                const float* p = &sQ[(wq + mt * 16 + (lane >> 2)) * DSTR + ks * 8 + (lane & 3)];
                afr[mt][0] = __float_as_uint(p[0]);
                afr[mt][1] = __float_as_uint(p[8 * DSTR]);
                afr[mt][2] = __float_as_uint(p[4]);
                afr[mt][3] = __float_as_uint(p[8 * DSTR + 4]);
            }
#pragma unroll
            for (int nt = 0; nt < 8; nt++) {
                const float* p = &sK[(nt * 8 + (lane >> 2)) * DSTR + ks * 8 + (lane & 3)];
                bfr[nt][0] = __float_as_uint(p[0]);
                bfr[nt][1] = __float_as_uint(p[4]);
            }
#pragma unroll
            for (int mt = 0; mt < 2; mt++)
#pragma unroll
                for (int nt = 0; nt < 8; nt++)
                    mma8(sacc[mt][nt], afr[mt], bfr[nt]);
        }

        // Online softmax (row stats shared across the lane-quad via shfl)
#pragma unroll
        for (int mt = 0; mt < 2; mt++) {
#pragma unroll
            for (int half = 0; half < 2; half++) {
                float mx = -1e30f;
#pragma unroll
                for (int nt = 0; nt < 8; nt++) {
                    mx = fmaxf(mx, sacc[mt][nt][half * 2]);
                    mx = fmaxf(mx, sacc[mt][nt][half * 2 + 1]);
                }
                mx = fmaxf(mx, __shfl_xor_sync(0xffffffffu, mx, 1));
                mx = fmaxf(mx, __shfl_xor_sync(0xffffffffu, mx, 2));
                float mold = mrow[mt][half];
                float mnew = fmaxf(mold, mx);
                float corr = __expf(mold - mnew);
                mrow[mt][half] = mnew;

                float s = 0.f;
#pragma unroll
                for (int nt = 0; nt < 8; nt++) {
                    float p0 = __expf(sacc[mt][nt][half * 2]     - mnew);
                    float p1 = __expf(sacc[mt][nt][half * 2 + 1] - mnew);
                    sacc[mt][nt][half * 2]     = p0;
                    sacc[mt][nt][half * 2 + 1] = p1;
                    s += p0 + p1;
                }
                s += __shfl_xor_sync(0xffffffffu, s, 1);
                s += __shfl_xor_sync(0xffffffffu, s, 2);
                lrow[mt][half] = lrow[mt][half] * corr + s;

#pragma unroll
                for (int nt = 0; nt < 8; nt++) {
                    oacc[mt][nt][half * 2]     *= corr;
                    oacc[mt][nt][half * 2 + 1] *= corr;
                }
                // P to smem (warp-local rows), tf32
                int r = wq + mt * 16 + half * 8 + (lane >> 2);
#pragma unroll
                for (int nt = 0; nt < 8; nt++) {
                    int c = nt * 8 + 2 * (lane & 3);
                    sP[r * DSTR + c]     = f2tff(sacc[mt][nt][half * 2]);
                    sP[r * DSTR + c + 1] = f2tff(sacc[mt][nt][half * 2 + 1]);
                }
            }
        }
        __syncwarp();

        // O += P @ V   (K = 64 keys, N = 64 dims)
#pragma unroll
        for (int ks = 0; ks < 8; ks++) {
            unsigned afr[2][4], bfr[8][2];
#pragma unroll
            for (int mt = 0; mt < 2; mt++) {
                const float* p = &sP[(wq + mt * 16 + (lane >> 2)) * DSTR + ks * 8 + (lane & 3)];
                afr[mt][0] = __float_as_uint(p[0]);
                afr[mt][1] = __float_as_uint(p[8 * DSTR]);
                afr[mt][2] = __float_as_uint(p[4]);
                afr[mt][3] = __float_as_uint(p[8 * DSTR + 4]);
            }
#pragma unroll
            for (int nt = 0; nt < 8; nt++) {
                const float* p = &sV[(ks * 8 + (lane & 3)) * DSTR + nt * 8 + (lane >> 2)];
                bfr[nt][0] = __float_as_uint(p[0]);
                bfr[nt][1] = __float_as_uint(p[4 * DSTR]);
            }
#pragma unroll
            for (int mt = 0; mt < 2; mt++)
#pragma unroll
                for (int nt = 0; nt < 8; nt++)
                    mma8(oacc[mt][nt], afr[mt], bfr[nt]);
        }
        __syncthreads();   // protect sK/sV before next chunk load
    }

    // Epilogue: normalize by l, write [B*T, E] with head offset
#pragma unroll
    for (int mt = 0; mt < 2; mt++) {
        int r0 = wq + mt * 16 + (lane >> 2);
        float inv0 = 1.f / lrow[mt][0];
        float inv1 = 1.f / lrow[mt][1];
#pragma unroll
        for (int nt = 0; nt < 8; nt++) {
            int c = nt * 8 + 2 * (lane & 3);
            size_t o0 = base + (size_t)(q0 + r0) * EDIM + c;
            Oa[o0]     = oacc[mt][nt][0] * inv0;
            Oa[o0 + 1] = oacc[mt][nt][1] * inv0;
            size_t o1 = base + (size_t)(q0 + r0 + 8) * EDIM + c;
            Oa[o1]     = oacc[mt][nt][2] * inv1;
            Oa[o1 + 1] = oacc[mt][nt][3] * inv1;
        }
    }
}

// ---------------------------------------------------------------------------
// Launch
// ---------------------------------------------------------------------------
extern "C" void kernel_launch(void* const* d_in, const int* in_sizes, int n_in,
                              void* d_out, int out_size)
{
    const float* x  = (const float*)d_in[0];
    const float* Wq = (const float*)d_in[1];
    const float* bq = (const float*)d_in[2];
    const float* Wk = (const float*)d_in[3];
    const float* bk = (const float*)d_in[4];
    const float* Wv = (const float*)d_in[5];
    const float* bv = (const float*)d_in[6];
    const float* Wo = (const float*)d_in[7];
    const float* bo = (const float*)d_in[8];
    float* out = (float*)d_out;

    float *Qp, *Kp, *Vp, *Ap;
    cudaGetSymbolAddress((void**)&Qp, g_Q);
    cudaGetSymbolAddress((void**)&Kp, g_K);
    cudaGetSymbolAddress((void**)&Vp, g_V);
    cudaGetSymbolAddress((void**)&Ap, g_A);

    const int ATTN_SMEM = (QT * DSTR + KC * DSTR + KC * DSTR + QT * DSTR) * (int)sizeof(float);
    cudaFuncSetAttribute(attn_kernel, cudaFuncAttributeMaxDynamicSharedMemorySize, ATTN_SMEM);

    dim3 ggrid(EDIM / BN, MTOT / BM);   // (8, 64)
    gemm_bias<<<ggrid, 256>>>(x, Wq, bq, Qp, EDIM, EDIM);
    gemm_bias<<<ggrid, 256>>>(x, Wk, bk, Kp, EDIM, EDIM);
    gemm_bias<<<ggrid, 256>>>(x, Wv, bv, Vp, EDIM, EDIM);

    dim3 agrid(T_SEQ / QT, BATCH * HEADS);  // (16, 64)
    attn_kernel<<<agrid, 128, ATTN_SMEM>>>(Qp, Kp, Vp, Ap);

    gemm_bias<<<ggrid, 256>>>(Ap, Wo, bo, out, EDIM, EDIM);
}

// round 5
// speedup vs baseline: 1.1008x; 1.1008x over previous
#include <cuda_runtime.h>
#include <math.h>

// Problem constants
#define BATCH 4
#define T_SEQ 2048
#define EDIM  1024
#define HEADS 16
#define HDIM  64
#define MTOT  (BATCH * T_SEQ)   // 8192 rows

// ---------------------------------------------------------------------------
// Scratch (allocation-free rule: __device__ globals)
// ---------------------------------------------------------------------------
__device__ float g_Q[(size_t)MTOT * EDIM];
__device__ float g_K[(size_t)MTOT * EDIM];
__device__ float g_V[(size_t)MTOT * EDIM];
__device__ float g_A[(size_t)MTOT * EDIM];
__device__ float g_X[(size_t)MTOT * EDIM];          // tf32-rounded X
__device__ float g_W[(size_t)4 * EDIM * EDIM];      // tf32-rounded Wq,Wk,Wv,Wo

// ---------------------------------------------------------------------------
// Helpers
// ---------------------------------------------------------------------------
__device__ __forceinline__ unsigned f2tf(float x) {
    unsigned u;
    asm("cvt.rna.tf32.f32 %0, %1;" : "=r"(u) : "f"(x));
    return u;
}
__device__ __forceinline__ float f2tff(float x) { return __uint_as_float(f2tf(x)); }

__device__ __forceinline__ void mma8(float* c, const unsigned* a, const unsigned* b) {
    asm volatile(
        "mma.sync.aligned.m16n8k8.row.col.f32.tf32.tf32.f32 "
        "{%0,%1,%2,%3}, {%4,%5,%6,%7}, {%8,%9}, {%0,%1,%2,%3};\n"
        : "+f"(c[0]), "+f"(c[1]), "+f"(c[2]), "+f"(c[3])
        : "r"(a[0]), "r"(a[1]), "r"(a[2]), "r"(a[3]), "r"(b[0]), "r"(b[1]));
}

__device__ __forceinline__ void cpa16(void* s, const void* g) {
    unsigned sa = (unsigned)__cvta_generic_to_shared(s);
    asm volatile("cp.async.cg.shared.global [%0], [%1], 16;\n" :: "r"(sa), "l"(g));
}
#define CP_COMMIT() asm volatile("cp.async.commit_group;\n" ::: "memory")
#define CP_WAIT0()  asm volatile("cp.async.wait_group 0;\n" ::: "memory")

// ---------------------------------------------------------------------------
// Elementwise RNA round-to-tf32
// ---------------------------------------------------------------------------
__global__ void round_tf32_kernel(const float* __restrict__ in, float* __restrict__ out, int n4)
{
    int i = blockIdx.x * blockDim.x + threadIdx.x;
    if (i < n4) {
        float4 v = reinterpret_cast<const float4*>(in)[i];
        v.x = f2tff(v.x); v.y = f2tff(v.y); v.z = f2tff(v.z); v.w = f2tff(v.w);
        reinterpret_cast<float4*>(out)[i] = v;
    }
}

// ---------------------------------------------------------------------------
// GEMM: Y[M,N] = X[M,K] @ W[N,K]^T + bias   (inputs pre-rounded to tf32)
// 128x128x32 tiles, 8 warps, cp.async double-buffered, 1 sync per k-tile.
// ---------------------------------------------------------------------------
#define BM 128
#define BN 128
#define BKC 32
#define ASTR 36                 // padded stride: fragment LDS conflict-free
#define GBUF (BM * ASTR + BN * ASTR)   // floats per stage buffer

__global__ __launch_bounds__(256, 2)
void gemm_bias(const float* __restrict__ X, const float* __restrict__ W,
               const float* __restrict__ bias, float* __restrict__ Y,
               int K, int N, int round_out)
{
    extern __shared__ float sm[];
    const int bm = blockIdx.y * BM;
    const int bn = blockIdx.x * BN;
    const int tid  = threadIdx.x;
    const int lane = tid & 31;
    const int warp = tid >> 5;
    const int wm = (warp >> 2) * 64;
    const int wn = (warp & 3) * 32;

    float acc[4][4][4];
#pragma unroll
    for (int mt = 0; mt < 4; mt++)
#pragma unroll
        for (int nt = 0; nt < 4; nt++)
#pragma unroll
            for (int r = 0; r < 4; r++) acc[mt][nt][r] = 0.f;

    const int NK = K / BKC;

    // stage k-tile 0 into buffer 0
    {
        float* As = sm;
        float* Bs = sm + BM * ASTR;
#pragma unroll
        for (int i = 0; i < 4; i++) {
            int idx = i * 256 + tid;
            int r = idx >> 3;
            int c = (idx & 7) * 4;
            cpa16(&As[r * ASTR + c], X + (size_t)(bm + r) * K + c);
            cpa16(&Bs[r * ASTR + c], W + (size_t)(bn + r) * K + c);
        }
        CP_COMMIT();
    }

    for (int kt = 0; kt < NK; kt++) {
        CP_WAIT0();
        __syncthreads();
        if (kt + 1 < NK) {
            float* As = sm + ((kt + 1) & 1) * GBUF;
            float* Bs = As + BM * ASTR;
            int kb = (kt + 1) * BKC;
#pragma unroll
            for (int i = 0; i < 4; i++) {
                int idx = i * 256 + tid;
                int r = idx >> 3;
                int c = (idx & 7) * 4;
                cpa16(&As[r * ASTR + c], X + (size_t)(bm + r) * K + kb + c);
                cpa16(&Bs[r * ASTR + c], W + (size_t)(bn + r) * K + kb + c);
            }
            CP_COMMIT();
        }

        const float* As = sm + (kt & 1) * GBUF;
        const float* Bs = As + BM * ASTR;
#pragma unroll
        for (int ks = 0; ks < 4; ks++) {
            unsigned afr[4][4], bfr[4][2];
#pragma unroll
            for (int mt = 0; mt < 4; mt++) {
                const float* p = &As[(wm + mt * 16 + (lane >> 2)) * ASTR + ks * 8 + (lane & 3)];
                afr[mt][0] = __float_as_uint(p[0]);
                afr[mt][1] = __float_as_uint(p[8 * ASTR]);
                afr[mt][2] = __float_as_uint(p[4]);
                afr[mt][3] = __float_as_uint(p[8 * ASTR + 4]);
            }
#pragma unroll
            for (int nt = 0; nt < 4; nt++) {
                const float* p = &Bs[(wn + nt * 8 + (lane >> 2)) * ASTR + ks * 8 + (lane & 3)];
                bfr[nt][0] = __float_as_uint(p[0]);
                bfr[nt][1] = __float_as_uint(p[4]);
            }
#pragma unroll
            for (int mt = 0; mt < 4; mt++)
#pragma unroll
                for (int nt = 0; nt < 4; nt++)
                    mma8(acc[mt][nt], afr[mt], bfr[nt]);
        }
    }

    // Epilogue: += bias; optionally round to tf32 (for Q/K/V/A buffers)
#pragma unroll
    for (int mt = 0; mt < 4; mt++) {
        int row = bm + wm + mt * 16 + (lane >> 2);
#pragma unroll
        for (int nt = 0; nt < 4; nt++) {
            int col = bn + wn + nt * 8 + 2 * (lane & 3);
            float b0 = bias[col], b1 = bias[col + 1];
            float v00 = acc[mt][nt][0] + b0, v01 = acc[mt][nt][1] + b1;
            float v10 = acc[mt][nt][2] + b0, v11 = acc[mt][nt][3] + b1;
            if (round_out) {
                v00 = f2tff(v00); v01 = f2tff(v01);
                v10 = f2tff(v10); v11 = f2tff(v11);
            }
            Y[(size_t)row * N + col]           = v00;
            Y[(size_t)row * N + col + 1]       = v01;
            Y[(size_t)(row + 8) * N + col]     = v10;
            Y[(size_t)(row + 8) * N + col + 1] = v11;
        }
    }
}

// ---------------------------------------------------------------------------
// Flash attention: per (b,h), 128-row Q tile, 64-key chunks.
// 8 warps x 16 q-rows. K/V double-buffered via cp.async. P never touches
// smem: C-frag -> A-frag via shfl transmute. Inputs pre-rounded tf32.
// ---------------------------------------------------------------------------
#define QT 128
#define KC 64
#define DSTR (HDIM + 4)   // 68, multiple of 4 (16B-aligned rows for cp.async)

__global__ __launch_bounds__(256, 2)
void attn_kernel(const float* __restrict__ Qg, const float* __restrict__ Kg,
                 const float* __restrict__ Vg, float* __restrict__ Oa)
{
    extern __shared__ float sm[];
    float* sQ = sm;                         // QT*DSTR
    float* sK = sQ + QT * DSTR;             // 2 * KC*DSTR
    float* sV = sK + 2 * KC * DSTR;         // 2 * KC*DSTR

    const int tid  = threadIdx.x;
    const int lane = tid & 31;
    const int warp = tid >> 5;
    const int bh = blockIdx.y;
    const int b  = bh >> 4;
    const int h  = bh & 15;
    const int q0 = blockIdx.x * QT;
    const size_t base = (size_t)b * T_SEQ * EDIM + (size_t)h * HDIM;
    const int wq = warp * 16;
    const int g = lane >> 2;
    const int q = lane & 3;

    // Stage Q (whole tile) + K/V chunk 0 into buffer 0
#pragma unroll
    for (int j = 0; j < 8; j++) {
        int i = j * 256 + tid;
        int r = i >> 4;
        int c = (i & 15) * 4;
        cpa16(&sQ[r * DSTR + c], Qg + base + (size_t)(q0 + r) * EDIM + c);
    }
#pragma unroll
    for (int j = 0; j < 4; j++) {
        int i = j * 256 + tid;
        int r = i >> 4;
        int c = (i & 15) * 4;
        cpa16(&sK[r * DSTR + c], Kg + base + (size_t)r * EDIM + c);
        cpa16(&sV[r * DSTR + c], Vg + base + (size_t)r * EDIM + c);
    }
    CP_COMMIT();

    float oacc[8][4];
#pragma unroll
    for (int nt = 0; nt < 8; nt++)
#pragma unroll
        for (int r = 0; r < 4; r++) oacc[nt][r] = 0.f;
    float mrow[2] = {-1e30f, -1e30f};
    float lrow[2] = {0.f, 0.f};

    const int NCHUNK = T_SEQ / KC;   // 32
    for (int ci = 0; ci < NCHUNK; ci++) {
        CP_WAIT0();
        __syncthreads();
        if (ci + 1 < NCHUNK) {
            float* dK = sK + ((ci + 1) & 1) * KC * DSTR;
            float* dV = sV + ((ci + 1) & 1) * KC * DSTR;
            int kc = (ci + 1) * KC;
#pragma unroll
            for (int j = 0; j < 4; j++) {
                int i = j * 256 + tid;
                int r = i >> 4;
                int c = (i & 15) * 4;
                cpa16(&dK[r * DSTR + c], Kg + base + (size_t)(kc + r) * EDIM + c);
                cpa16(&dV[r * DSTR + c], Vg + base + (size_t)(kc + r) * EDIM + c);
            }
            CP_COMMIT();
        }

        const float* cK = sK + (ci & 1) * KC * DSTR;
        const float* cV = sV + (ci & 1) * KC * DSTR;

        // S = Q @ K^T   (16 rows/warp x 64 keys, K-dim 64)
        float sacc[8][4];
#pragma unroll
        for (int nt = 0; nt < 8; nt++)
#pragma unroll
            for (int r = 0; r < 4; r++) sacc[nt][r] = 0.f;

#pragma unroll
        for (int ks = 0; ks < 8; ks++) {
            unsigned afr[4], bfr[8][2];
            {
                const float* p = &sQ[(wq + g) * DSTR + ks * 8 + q];
                afr[0] = __float_as_uint(p[0]);
                afr[1] = __float_as_uint(p[8 * DSTR]);
                afr[2] = __float_as_uint(p[4]);
                afr[3] = __float_as_uint(p[8 * DSTR + 4]);
            }
#pragma unroll
            for (int nt = 0; nt < 8; nt++) {
                const float* p = &cK[(nt * 8 + g) * DSTR + ks * 8 + q];
                bfr[nt][0] = __float_as_uint(p[0]);
                bfr[nt][1] = __float_as_uint(p[4]);
            }
#pragma unroll
            for (int nt = 0; nt < 8; nt++)
                mma8(sacc[nt], afr, bfr[nt]);
        }

        // scale by 1/sqrt(D)
#pragma unroll
        for (int nt = 0; nt < 8; nt++)
#pragma unroll
            for (int r = 0; r < 4; r++) sacc[nt][r] *= 0.125f;

        // Online softmax (row stats across the lane-quad via shfl)
#pragma unroll
        for (int half = 0; half < 2; half++) {
            float mx = -1e30f;
#pragma unroll
            for (int nt = 0; nt < 8; nt++) {
                mx = fmaxf(mx, sacc[nt][half * 2]);
                mx = fmaxf(mx, sacc[nt][half * 2 + 1]);
            }
            mx = fmaxf(mx, __shfl_xor_sync(0xffffffffu, mx, 1));
            mx = fmaxf(mx, __shfl_xor_sync(0xffffffffu, mx, 2));
            float mold = mrow[half];
            float mnew = fmaxf(mold, mx);
            float corr = __expf(mold - mnew);
            mrow[half] = mnew;

            float s = 0.f;
#pragma unroll
            for (int nt = 0; nt < 8; nt++) {
                float p0 = __expf(sacc[nt][half * 2]     - mnew);
                float p1 = __expf(sacc[nt][half * 2 + 1] - mnew);
                sacc[nt][half * 2]     = p0;
                sacc[nt][half * 2 + 1] = p1;
                s += p0 + p1;
            }
            s += __shfl_xor_sync(0xffffffffu, s, 1);
            s += __shfl_xor_sync(0xffffffffu, s, 2);
            lrow[half] = lrow[half] * corr + s;

#pragma unroll
            for (int nt = 0; nt < 8; nt++) {
                oacc[nt][half * 2]     *= corr;
                oacc[nt][half * 2 + 1] *= corr;
            }
        }

        // O += P @ V : transmute C-frag of P into A-frag via shfl (no smem)
        const int s_lo = (lane & 28) | (q >> 1);
        const int s_hi = s_lo | 2;
        const bool odd = q & 1;
#pragma unroll
        for (int ks = 0; ks < 8; ks++) {
            float c0 = sacc[ks][0], c1 = sacc[ks][1];
            float c2 = sacc[ks][2], c3 = sacc[ks][3];
            float t0 = __shfl_sync(0xffffffffu, c0, s_lo);
            float t1 = __shfl_sync(0xffffffffu, c1, s_lo);
            float u0 = __shfl_sync(0xffffffffu, c0, s_hi);
            float u1 = __shfl_sync(0xffffffffu, c1, s_hi);
            float t2 = __shfl_sync(0xffffffffu, c2, s_lo);
            float t3 = __shfl_sync(0xffffffffu, c3, s_lo);
            float u2 = __shfl_sync(0xffffffffu, c2, s_hi);
            float u3 = __shfl_sync(0xffffffffu, c3, s_hi);
            unsigned afr[4];
            afr[0] = f2tf(odd ? t1 : t0);
            afr[1] = f2tf(odd ? t3 : t2);
            afr[2] = f2tf(odd ? u1 : u0);
            afr[3] = f2tf(odd ? u3 : u2);

            unsigned bfr[8][2];
#pragma unroll
            for (int nt = 0; nt < 8; nt++) {
                const float* p = &cV[(ks * 8 + q) * DSTR + nt * 8 + g];
                bfr[nt][0] = __float_as_uint(p[0]);
                bfr[nt][1] = __float_as_uint(p[4 * DSTR]);
            }
#pragma unroll
            for (int nt = 0; nt < 8; nt++)
                mma8(oacc[nt], afr, bfr[nt]);
        }
    }

    // Epilogue: normalize, round to tf32 (A feeds final GEMM), store
    float inv0 = 1.f / lrow[0];
    float inv1 = 1.f / lrow[1];
    int r0 = wq + g;
#pragma unroll
    for (int nt = 0; nt < 8; nt++) {
        int c = nt * 8 + 2 * q;
        size_t o0 = base + (size_t)(q0 + r0) * EDIM + c;
        Oa[o0]     = f2tff(oacc[nt][0] * inv0);
        Oa[o0 + 1] = f2tff(oacc[nt][1] * inv0);
        size_t o1 = base + (size_t)(q0 + r0 + 8) * EDIM + c;
        Oa[o1]     = f2tff(oacc[nt][2] * inv1);
        Oa[o1 + 1] = f2tff(oacc[nt][3] * inv1);
    }
}

// ---------------------------------------------------------------------------
// Launch
// ---------------------------------------------------------------------------
extern "C" void kernel_launch(void* const* d_in, const int* in_sizes, int n_in,
                              void* d_out, int out_size)
{
    const float* x  = (const float*)d_in[0];
    const float* Wq = (const float*)d_in[1];
    const float* bq = (const float*)d_in[2];
    const float* Wk = (const float*)d_in[3];
    const float* bk = (const float*)d_in[4];
    const float* Wv = (const float*)d_in[5];
    const float* bv = (const float*)d_in[6];
    const float* Wo = (const float*)d_in[7];
    const float* bo = (const float*)d_in[8];
    float* out = (float*)d_out;

    float *Qp, *Kp, *Vp, *Ap, *Xp, *Wp;
    cudaGetSymbolAddress((void**)&Qp, g_Q);
    cudaGetSymbolAddress((void**)&Kp, g_K);
    cudaGetSymbolAddress((void**)&Vp, g_V);
    cudaGetSymbolAddress((void**)&Ap, g_A);
    cudaGetSymbolAddress((void**)&Xp, g_X);
    cudaGetSymbolAddress((void**)&Wp, g_W);

    const int GEMM_SMEM = 2 * GBUF * (int)sizeof(float);                    // 73728
    const int ATTN_SMEM = (QT * DSTR + 4 * KC * DSTR) * (int)sizeof(float); // 104448
    cudaFuncSetAttribute(gemm_bias, cudaFuncAttributeMaxDynamicSharedMemorySize, GEMM_SMEM);
    cudaFuncSetAttribute(attn_kernel, cudaFuncAttributeMaxDynamicSharedMemorySize, ATTN_SMEM);

    const size_t WSZ = (size_t)EDIM * EDIM;

    // Pre-round inputs to tf32 (RNA) so cp.async can stage raw bits
    {
        int n4x = (int)((size_t)MTOT * EDIM / 4);
        round_tf32_kernel<<<(n4x + 255) / 256, 256>>>(x, Xp, n4x);
        int n4w = (int)(WSZ / 4);
        round_tf32_kernel<<<(n4w + 255) / 256, 256>>>(Wq, Wp + 0 * WSZ, n4w);
        round_tf32_kernel<<<(n4w + 255) / 256, 256>>>(Wk, Wp + 1 * WSZ, n4w);
        round_tf32_kernel<<<(n4w + 255) / 256, 256>>>(Wv, Wp + 2 * WSZ, n4w);
        round_tf32_kernel<<<(n4w + 255) / 256, 256>>>(Wo, Wp + 3 * WSZ, n4w);
    }

    dim3 ggrid(EDIM / BN, MTOT / BM);   // (8, 64)
    gemm_bias<<<ggrid, 256, GEMM_SMEM>>>(Xp, Wp + 0 * WSZ, bq, Qp, EDIM, EDIM, 1);
    gemm_bias<<<ggrid, 256, GEMM_SMEM>>>(Xp, Wp + 1 * WSZ, bk, Kp, EDIM, EDIM, 1);
    gemm_bias<<<ggrid, 256, GEMM_SMEM>>>(Xp, Wp + 2 * WSZ, bv, Vp, EDIM, EDIM, 1);

    dim3 agrid(T_SEQ / QT, BATCH * HEADS);  // (16, 64)
    attn_kernel<<<agrid, 256, ATTN_SMEM>>>(Qp, Kp, Vp, Ap);

    gemm_bias<<<ggrid, 256, GEMM_SMEM>>>(Ap, Wp + 3 * WSZ, bo, out, EDIM, EDIM, 0);
}

// round 10
// speedup vs baseline: 2.1487x; 1.9520x over previous
#include <cuda_runtime.h>
#include <cuda_fp16.h>
#include <stdint.h>
#include <math.h>

// Problem constants
#define BATCH 4
#define T_SEQ 2048
#define EDIM  1024
#define HEADS 16
#define HDIM  64
#define MTOT  (BATCH * T_SEQ)   // 8192 rows

// ---------------------------------------------------------------------------
// Scratch (allocation-free rule: __device__ globals) — all fp16
// ---------------------------------------------------------------------------
__device__ __half g_Xh[(size_t)MTOT * EDIM];
__device__ __half g_Wh[(size_t)4 * EDIM * EDIM];
__device__ __half g_Qh[(size_t)MTOT * EDIM];
__device__ __half g_Kh[(size_t)MTOT * EDIM];
__device__ __half g_Vh[(size_t)MTOT * EDIM];
__device__ __half g_Vt[(size_t)MTOT * EDIM];   // per (b,h): [d][t]
__device__ __half g_Ah[(size_t)MTOT * EDIM];

// ---------------------------------------------------------------------------
// Helpers
// ---------------------------------------------------------------------------
__device__ __forceinline__ unsigned packh2(float a, float b) {
    __half2 h = __floats2half2_rn(a, b);
    return *reinterpret_cast<unsigned*>(&h);
}

// fp16 mma: D(f32) += A(f16 16x16) * B(f16 16x8, col-major)
__device__ __forceinline__ void mma16(float* c, const unsigned* a, const unsigned* b) {
    asm volatile(
        "mma.sync.aligned.m16n8k16.row.col.f32.f16.f16.f32 "
        "{%0,%1,%2,%3}, {%4,%5,%6,%7}, {%8,%9}, {%0,%1,%2,%3};\n"
        : "+f"(c[0]), "+f"(c[1]), "+f"(c[2]), "+f"(c[3])
        : "r"(a[0]), "r"(a[1]), "r"(a[2]), "r"(a[3]), "r"(b[0]), "r"(b[1]));
}

__device__ __forceinline__ void cpa16(void* s, const void* g) {
    unsigned sa = (unsigned)__cvta_generic_to_shared(s);
    asm volatile("cp.async.cg.shared.global [%0], [%1], 16;\n" :: "r"(sa), "l"(g));
}
#define CP_COMMIT() asm volatile("cp.async.commit_group;\n" ::: "memory")
#define CP_WAIT0()  asm volatile("cp.async.wait_group 0;\n" ::: "memory")

// ---------------------------------------------------------------------------
// f32 -> f16 convert (RN)
// ---------------------------------------------------------------------------
__global__ void f32_to_f16_kernel(const float* __restrict__ in, __half* __restrict__ out, int n4)
{
    int i = blockIdx.x * blockDim.x + threadIdx.x;
    if (i < n4) {
        float4 v = reinterpret_cast<const float4*>(in)[i];
        __half2 h0 = __floats2half2_rn(v.x, v.y);
        __half2 h1 = __floats2half2_rn(v.z, v.w);
        reinterpret_cast<__half2*>(out)[i * 2 + 0] = h0;
        reinterpret_cast<__half2*>(out)[i * 2 + 1] = h1;
    }
}

// ---------------------------------------------------------------------------
// V transpose: Vh [token][E] (head slice) -> Vt per (b,h): [d][t]
// ---------------------------------------------------------------------------
__global__ __launch_bounds__(256)
void transpose_v_kernel(const __half* __restrict__ Vh, __half* __restrict__ Vt)
{
    __shared__ __half tile[64][72];
    const int bh = blockIdx.y;
    const int b  = bh >> 4;
    const int h  = bh & 15;
    const int t0 = blockIdx.x * 64;
    const int tid = threadIdx.x;

    for (int i = tid; i < 512; i += 256) {
        int t = i >> 3, c = (i & 7) * 8;
        *reinterpret_cast<uint4*>(&tile[t][c]) =
            *reinterpret_cast<const uint4*>(Vh + ((size_t)(b * T_SEQ + t0 + t)) * EDIM + h * HDIM + c);
    }
    __syncthreads();
    for (int i = tid; i < 512; i += 256) {
        int d = i >> 3, c = (i & 7) * 8;
        __half tmp[8];
#pragma unroll
        for (int k = 0; k < 8; k++) tmp[k] = tile[c + k][d];
        *reinterpret_cast<uint4*>(Vt + ((size_t)(bh * HDIM + d)) * T_SEQ + t0 + c) =
            *reinterpret_cast<uint4*>(tmp);
    }
}

// ---------------------------------------------------------------------------
// fp16 GEMM: Y[M,N] = X[M,K] @ W[N,K]^T + bias
// 128x128 tile, K-chunk 64 halves (128B rows), double-buffered cp.async,
// 8 warps (2x4), warp tile 64x32, m16n8k16.
// mode: 0 = f32 output, 1 = f16 output
// ---------------------------------------------------------------------------
#define BM 128
#define BN 128
#define BKH 64                   // K-chunk in halves
#define GSTR 72                  // padded row stride (halves), 144B
#define GSTAGE ((BM + BN) * GSTR)   // halves per stage

__global__ __launch_bounds__(256, 2)
void gemm_h(const __half* __restrict__ X, const __half* __restrict__ W,
            const float* __restrict__ bias, void* __restrict__ Yv,
            int K, int N, int mode)
{
    extern __shared__ __half smh[];
    const int bm = blockIdx.y * BM;
    const int bn = blockIdx.x * BN;
    const int tid  = threadIdx.x;
    const int lane = tid & 31;
    const int warp = tid >> 5;
    const int wm = (warp >> 2) * 64;
    const int wn = (warp & 3) * 32;
    const int g = lane >> 2;
    const int q = lane & 3;

    float acc[4][4][4];
#pragma unroll
    for (int mt = 0; mt < 4; mt++)
#pragma unroll
        for (int nt = 0; nt < 4; nt++)
#pragma unroll
            for (int r = 0; r < 4; r++) acc[mt][nt][r] = 0.f;

    const int NK = K / BKH;   // 16

    auto stage = [&](int chunk, int s) {
        __half* A = smh + s * GSTAGE;
        __half* B = A + BM * GSTR;
        const __half* xp = X + (size_t)bm * K + chunk * BKH;
        const __half* wp = W + (size_t)bn * K + chunk * BKH;
#pragma unroll
        for (int j = 0; j < 4; j++) {
            int idx = j * 256 + tid;
            int r = idx >> 3;
            int c = (idx & 7) * 8;
            cpa16(&A[r * GSTR + c], xp + (size_t)r * K + c);
            cpa16(&B[r * GSTR + c], wp + (size_t)r * K + c);
        }
        CP_COMMIT();
    };

    stage(0, 0);

    for (int kt = 0; kt < NK; kt++) {
        CP_WAIT0();
        __syncthreads();
        if (kt + 1 < NK) stage(kt + 1, (kt + 1) & 1);

        const __half* As = smh + (kt & 1) * GSTAGE;
        const __half* Bs = As + BM * GSTR;
#pragma unroll
        for (int kk = 0; kk < 4; kk++) {          // 4 x k16
            unsigned afr[4][4], bfr[4][2];
#pragma unroll
            for (int mt = 0; mt < 4; mt++) {
                const __half* p = &As[(wm + mt * 16 + g) * GSTR + kk * 16 + 2 * q];
                afr[mt][0] = *reinterpret_cast<const unsigned*>(p);
                afr[mt][1] = *reinterpret_cast<const unsigned*>(p + 8 * GSTR);
                afr[mt][2] = *reinterpret_cast<const unsigned*>(p + 8);
                afr[mt][3] = *reinterpret_cast<const unsigned*>(p + 8 * GSTR + 8);
            }
#pragma unroll
            for (int nt = 0; nt < 4; nt++) {
                const __half* p = &Bs[(wn + nt * 8 + g) * GSTR + kk * 16 + 2 * q];
                bfr[nt][0] = *reinterpret_cast<const unsigned*>(p);
                bfr[nt][1] = *reinterpret_cast<const unsigned*>(p + 8);
            }
#pragma unroll
            for (int mt = 0; mt < 4; mt++)
#pragma unroll
                for (int nt = 0; nt < 4; nt++)
                    mma16(acc[mt][nt], afr[mt], bfr[nt]);
        }
        __syncthreads();
    }

    // Epilogue
#pragma unroll
    for (int mt = 0; mt < 4; mt++) {
        int row = bm + wm + mt * 16 + g;
#pragma unroll
        for (int nt = 0; nt < 4; nt++) {
            int col = bn + wn + nt * 8 + 2 * q;
            float b0 = bias[col], b1 = bias[col + 1];
            float v00 = acc[mt][nt][0] + b0, v01 = acc[mt][nt][1] + b1;
            float v10 = acc[mt][nt][2] + b0, v11 = acc[mt][nt][3] + b1;
            if (mode) {
                __half* Y = (__half*)Yv;
                *reinterpret_cast<__half2*>(Y + (size_t)row * N + col) = __floats2half2_rn(v00, v01);
                *reinterpret_cast<__half2*>(Y + (size_t)(row + 8) * N + col) = __floats2half2_rn(v10, v11);
            } else {
                float* Y = (float*)Yv;
                *reinterpret_cast<float2*>(Y + (size_t)row * N + col) = make_float2(v00, v01);
                *reinterpret_cast<float2*>(Y + (size_t)(row + 8) * N + col) = make_float2(v10, v11);
            }
        }
    }
}

// ---------------------------------------------------------------------------
// fp16 flash attention: per (b,h), 128-row Q tile, 64-key chunks.
// 8 warps x 16 q-rows. K/Vt double-buffered cp.async. P C-frag == A-frag
// under k16 layout: pack-to-half2, no shuffles. Softmax fp32.
// ---------------------------------------------------------------------------
#define QT 128
#define KC 64
#define QSTR 72    // halves, 144B

__global__ __launch_bounds__(256, 2)
void attn_kernel(const __half* __restrict__ Qh, const __half* __restrict__ Kh,
                 const __half* __restrict__ Vt, __half* __restrict__ Ah)
{
    extern __shared__ __half smh[];
    __half* sQ = smh;                          // QT*QSTR
    __half* sK = sQ + QT * QSTR;               // 2 * KC*QSTR
    __half* sV = sK + 2 * KC * QSTR;           // 2 * KC*QSTR  (rows = d)

    const int tid  = threadIdx.x;
    const int lane = tid & 31;
    const int warp = tid >> 5;
    const int bh = blockIdx.y;
    const int b  = bh >> 4;
    const int h  = bh & 15;
    const int q0 = blockIdx.x * QT;
    const size_t baseTok = (size_t)b * T_SEQ * EDIM + (size_t)h * HDIM;
    const size_t baseVt  = (size_t)bh * HDIM * T_SEQ;
    const int wq = warp * 16;
    const int g = lane >> 2;
    const int q = lane & 3;

    // Stage Q (whole tile) + chunk 0 of K and Vt
#pragma unroll
    for (int j = 0; j < 4; j++) {
        int i = j * 256 + tid;
        int r = i >> 3;
        int c = (i & 7) * 8;
        cpa16(&sQ[r * QSTR + c], Qh + baseTok + (size_t)(q0 + r) * EDIM + c);
    }
#pragma unroll
    for (int j = 0; j < 2; j++) {
        int i = j * 256 + tid;
        int r = i >> 3;
        int c = (i & 7) * 8;
        cpa16(&sK[r * QSTR + c], Kh + baseTok + (size_t)r * EDIM + c);
        cpa16(&sV[r * QSTR + c], Vt + baseVt + (size_t)r * T_SEQ + c);
    }
    CP_COMMIT();

    float oacc[8][4];
#pragma unroll
    for (int nt = 0; nt < 8; nt++)
#pragma unroll
        for (int r = 0; r < 4; r++) oacc[nt][r] = 0.f;
    float mrow[2] = {-1e30f, -1e30f};
    float lrow[2] = {0.f, 0.f};

    const int NCHUNK = T_SEQ / KC;   // 32
    for (int ci = 0; ci < NCHUNK; ci++) {
        CP_WAIT0();
        __syncthreads();
        if (ci + 1 < NCHUNK) {
            __half* dK = sK + ((ci + 1) & 1) * KC * QSTR;
            __half* dV = sV + ((ci + 1) & 1) * KC * QSTR;
            int kc = (ci + 1) * KC;
#pragma unroll
            for (int j = 0; j < 2; j++) {
                int i = j * 256 + tid;
                int r = i >> 3;
                int c = (i & 7) * 8;
                cpa16(&dK[r * QSTR + c], Kh + baseTok + (size_t)(kc + r) * EDIM + c);
                cpa16(&dV[r * QSTR + c], Vt + baseVt + (size_t)r * T_SEQ + kc + c);
            }
            CP_COMMIT();
        }

        const __half* cK = sK + (ci & 1) * KC * QSTR;
        const __half* cV = sV + (ci & 1) * KC * QSTR;

        // S = Q @ K^T  (16 rows/warp x 64 keys, d = 4 x k16)
        float sacc[8][4];
#pragma unroll
        for (int nt = 0; nt < 8; nt++)
#pragma unroll
            for (int r = 0; r < 4; r++) sacc[nt][r] = 0.f;

#pragma unroll
        for (int ks = 0; ks < 4; ks++) {
            unsigned afr[4], bfr[8][2];
            {
                const __half* p = &sQ[(wq + g) * QSTR + ks * 16 + 2 * q];
                afr[0] = *reinterpret_cast<const unsigned*>(p);
                afr[1] = *reinterpret_cast<const unsigned*>(p + 8 * QSTR);
                afr[2] = *reinterpret_cast<const unsigned*>(p + 8);
                afr[3] = *reinterpret_cast<const unsigned*>(p + 8 * QSTR + 8);
            }
#pragma unroll
            for (int nt = 0; nt < 8; nt++) {
                const __half* p = &cK[(nt * 8 + g) * QSTR + ks * 16 + 2 * q];
                bfr[nt][0] = *reinterpret_cast<const unsigned*>(p);
                bfr[nt][1] = *reinterpret_cast<const unsigned*>(p + 8);
            }
#pragma unroll
            for (int nt = 0; nt < 8; nt++)
                mma16(sacc[nt], afr, bfr[nt]);
        }

        // scale 1/sqrt(D)
#pragma unroll
        for (int nt = 0; nt < 8; nt++)
#pragma unroll
            for (int r = 0; r < 4; r++) sacc[nt][r] *= 0.125f;

        // Online softmax (fp32, lane-quad reduction)
#pragma unroll
        for (int half = 0; half < 2; half++) {
            float mx = -1e30f;
#pragma unroll
            for (int nt = 0; nt < 8; nt++) {
                mx = fmaxf(mx, sacc[nt][half * 2]);
                mx = fmaxf(mx, sacc[nt][half * 2 + 1]);
            }
            mx = fmaxf(mx, __shfl_xor_sync(0xffffffffu, mx, 1));
            mx = fmaxf(mx, __shfl_xor_sync(0xffffffffu, mx, 2));
            float mold = mrow[half];
            float mnew = fmaxf(mold, mx);
            float corr = __expf(mold - mnew);
            mrow[half] = mnew;

            float s = 0.f;
#pragma unroll
            for (int nt = 0; nt < 8; nt++) {
                float p0 = __expf(sacc[nt][half * 2]     - mnew);
                float p1 = __expf(sacc[nt][half * 2 + 1] - mnew);
                sacc[nt][half * 2]     = p0;
                sacc[nt][half * 2 + 1] = p1;
                s += p0 + p1;
            }
            s += __shfl_xor_sync(0xffffffffu, s, 1);
            s += __shfl_xor_sync(0xffffffffu, s, 2);
            lrow[half] = lrow[half] * corr + s;

#pragma unroll
            for (int nt = 0; nt < 8; nt++) {
                oacc[nt][half * 2]     *= corr;
                oacc[nt][half * 2 + 1] *= corr;
            }
        }

        // O += P @ V : P's k16 A-frag == its C-frag (pack only, no shfl)
#pragma unroll
        for (int ks = 0; ks < 4; ks++) {
            unsigned afr[4];
            afr[0] = packh2(sacc[2 * ks][0],     sacc[2 * ks][1]);
            afr[1] = packh2(sacc[2 * ks][2],     sacc[2 * ks][3]);
            afr[2] = packh2(sacc[2 * ks + 1][0], sacc[2 * ks + 1][1]);
            afr[3] = packh2(sacc[2 * ks + 1][2], sacc[2 * ks + 1][3]);

            unsigned bfr[8][2];
#pragma unroll
            for (int nt = 0; nt < 8; nt++) {
                const __half* p = &cV[(nt * 8 + g) * QSTR + ks * 16 + 2 * q];
                bfr[nt][0] = *reinterpret_cast<const unsigned*>(p);
                bfr[nt][1] = *reinterpret_cast<const unsigned*>(p + 8);
            }
#pragma unroll
            for (int nt = 0; nt < 8; nt++)
                mma16(oacc[nt], afr, bfr[nt]);
        }
    }

    // Epilogue: normalize, store fp16 A
    float inv0 = 1.f / lrow[0];
    float inv1 = 1.f / lrow[1];
    int r0 = wq + g;
#pragma unroll
    for (int nt = 0; nt < 8; nt++) {
        int c = nt * 8 + 2 * q;
        size_t o0 = baseTok + (size_t)(q0 + r0) * EDIM + c;
        *reinterpret_cast<__half2*>(Ah + o0) =
            __floats2half2_rn(oacc[nt][0] * inv0, oacc[nt][1] * inv0);
        size_t o1 = baseTok + (size_t)(q0 + r0 + 8) * EDIM + c;
        *reinterpret_cast<__half2*>(Ah + o1) =
            __floats2half2_rn(oacc[nt][2] * inv1, oacc[nt][3] * inv1);
    }
}

// ---------------------------------------------------------------------------
// Launch
// ---------------------------------------------------------------------------
extern "C" void kernel_launch(void* const* d_in, const int* in_sizes, int n_in,
                              void* d_out, int out_size)
{
    const float* x  = (const float*)d_in[0];
    const float* Wq = (const float*)d_in[1];
    const float* bq = (const float*)d_in[2];
    const float* Wk = (const float*)d_in[3];
    const float* bk = (const float*)d_in[4];
    const float* Wv = (const float*)d_in[5];
    const float* bv = (const float*)d_in[6];
    const float* Wo = (const float*)d_in[7];
    const float* bo = (const float*)d_in[8];
    float* out = (float*)d_out;

    __half *Xh, *Wh, *Qh, *Kh, *Vh, *Vt, *Ah;
    cudaGetSymbolAddress((void**)&Xh, g_Xh);
    cudaGetSymbolAddress((void**)&Wh, g_Wh);
    cudaGetSymbolAddress((void**)&Qh, g_Qh);
    cudaGetSymbolAddress((void**)&Kh, g_Kh);
    cudaGetSymbolAddress((void**)&Vh, g_Vh);
    cudaGetSymbolAddress((void**)&Vt, g_Vt);
    cudaGetSymbolAddress((void**)&Ah, g_Ah);

    const int GEMM_SMEM = 2 * GSTAGE * (int)sizeof(__half);                  // 73728
    const int ATTN_SMEM = (QT * QSTR + 4 * KC * QSTR) * (int)sizeof(__half); // 55296
    cudaFuncSetAttribute(gemm_h, cudaFuncAttributeMaxDynamicSharedMemorySize, GEMM_SMEM);
    cudaFuncSetAttribute(attn_kernel, cudaFuncAttributeMaxDynamicSharedMemorySize, ATTN_SMEM);

    const size_t WSZ = (size_t)EDIM * EDIM;

    // Convert inputs to fp16
    {
        int n4x = (int)((size_t)MTOT * EDIM / 4);
        f32_to_f16_kernel<<<(n4x + 255) / 256, 256>>>(x, Xh, n4x);
        int n4w = (int)(WSZ / 4);
        f32_to_f16_kernel<<<(n4w + 255) / 256, 256>>>(Wq, Wh + 0 * WSZ, n4w);
        f32_to_f16_kernel<<<(n4w + 255) / 256, 256>>>(Wk, Wh + 1 * WSZ, n4w);
        f32_to_f16_kernel<<<(n4w + 255) / 256, 256>>>(Wv, Wh + 2 * WSZ, n4w);
        f32_to_f16_kernel<<<(n4w + 255) / 256, 256>>>(Wo, Wh + 3 * WSZ, n4w);
    }

    dim3 ggrid(EDIM / BN, MTOT / BM);   // (8, 64)
    gemm_h<<<ggrid, 256, GEMM_SMEM>>>(Xh, Wh + 0 * WSZ, bq, Qh, EDIM, EDIM, 1);
    gemm_h<<<ggrid, 256, GEMM_SMEM>>>(Xh, Wh + 1 * WSZ, bk, Kh, EDIM, EDIM, 1);
    gemm_h<<<ggrid, 256, GEMM_SMEM>>>(Xh, Wh + 2 * WSZ, bv, Vh, EDIM, EDIM, 1);

    dim3 tgrid(T_SEQ / 64, BATCH * HEADS);  // (32, 64)
    transpose_v_kernel<<<tgrid, 256>>>(Vh, Vt);

    dim3 agrid(T_SEQ / QT, BATCH * HEADS);  // (16, 64)
    attn_kernel<<<agrid, 256, ATTN_SMEM>>>(Qh, Kh, Vt, Ah);

    gemm_h<<<ggrid, 256, GEMM_SMEM>>>(Ah, Wh + 3 * WSZ, bo, out, EDIM, EDIM, 0);
}